// round 9
// baseline (speedup 1.0000x reference)
#include <cuda_runtime.h>
#include <math.h>

#define NE   65536
#define DIM  512
#define DFF  2048
#define LN_EPS 1e-5f

typedef unsigned short u16;
typedef unsigned int   u32;

// ---------------- scratch (device globals; no allocations) ----------------
__device__ __align__(16) float g_qs [(size_t)NE * DIM];
__device__ __align__(16) float g_ks [(size_t)NE * DIM];
__device__ __align__(16) float g_vs [(size_t)NE * DIM];
__device__ __align__(16) u16 g_aq_h[(size_t)NE * DIM];  // ln_qry, later attn_output
__device__ __align__(16) u16 g_aq_l[(size_t)NE * DIM];
__device__ __align__(16) u16 g_as_h[(size_t)NE * DIM];  // ln_src, later y (ln2 out)
__device__ __align__(16) u16 g_as_l[(size_t)NE * DIM];
__device__ __align__(16) u16 g_ff_h[(size_t)NE * DFF];  // gelu output
__device__ __align__(16) u16 g_ff_l[(size_t)NE * DFF];
// weights stored TRANSPOSED: Wt[n*K + k], split hi/lo
#define OFF_Q 0
#define OFF_K (512*512)
#define OFF_V (2*512*512)
#define OFF_H (3*512*512)
#define OFF_1 (4*512*512)
#define OFF_2 (4*512*512 + 512*2048)
#define W_TOT (4*512*512 + 2*512*2048)
__device__ __align__(16) u16 g_w_h[W_TOT];
__device__ __align__(16) u16 g_w_l[W_TOT];
// [0,DIM)=diag  [DIM,2DIM)=ksum  [2DIM]=|qs|^2  [2DIM+1]=|ks|^2
__device__ __align__(16) float g_red[2 * DIM + 8];

// ---------------- bf16-as-bits helpers ----------------
__device__ __forceinline__ u16 f2bf(float x) {
    u32 u = __float_as_uint(x);
    u32 r = u + 0x7FFFu + ((u >> 16) & 1u);   // round-to-nearest-even
    return (u16)(r >> 16);
}
__device__ __forceinline__ float bf2f(u16 h) {
    return __uint_as_float(((u32)h) << 16);
}
__device__ __forceinline__ void split1(float x, u16& h, u16& l) {
    h = f2bf(x);
    l = f2bf(x - bf2f(h));
}
__device__ __forceinline__ u32 pack2(u16 a, u16 b) {
    return (u32)a | ((u32)b << 16);
}

__device__ __forceinline__ u32 smem_u32(const void* p) {
    return (u32)__cvta_generic_to_shared(p);
}
__device__ __forceinline__ void ldsm_x4(u32* r, u32 a) {
    asm volatile("ldmatrix.sync.aligned.m8n8.x4.shared.b16 {%0,%1,%2,%3}, [%4];"
                 : "=r"(r[0]), "=r"(r[1]), "=r"(r[2]), "=r"(r[3]) : "r"(a));
}
__device__ __forceinline__ void mma16816(float* d, const u32* a, const u32* b) {
    asm volatile("mma.sync.aligned.m16n8k16.row.col.f32.bf16.bf16.f32 "
                 "{%0,%1,%2,%3}, {%4,%5,%6,%7}, {%8,%9}, {%0,%1,%2,%3};"
                 : "+f"(d[0]), "+f"(d[1]), "+f"(d[2]), "+f"(d[3])
                 : "r"(a[0]), "r"(a[1]), "r"(a[2]), "r"(a[3]), "r"(b[0]), "r"(b[1]));
}
__device__ __forceinline__ void cpa16(u32 dst, const void* src) {
    asm volatile("cp.async.cg.shared.global [%0], [%1], 16;" :: "r"(dst), "l"(src));
}
__device__ __forceinline__ void cp_commit() {
    asm volatile("cp.async.commit_group;");
}
template <int N>
__device__ __forceinline__ void cp_wait() {
    asm volatile("cp.async.wait_group %0;" :: "n"(N));
}

// ---------------- small kernels ----------------
__global__ void zero_red_kernel() {
    int i = blockIdx.x * blockDim.x + threadIdx.x;
    if (i < 2 * DIM + 8) g_red[i] = 0.0f;
}

// transpose + split: W[K][N] -> Wt[N][K] (hi/lo).  grid (N/32, K/32), block (32,8)
__global__ void wsplit_t_kernel(const float* __restrict__ src, int off, int K, int N) {
    __shared__ float tile[32][33];
    int n0 = blockIdx.x * 32, k0 = blockIdx.y * 32;
    int tx = threadIdx.x, ty = threadIdx.y;
    #pragma unroll
    for (int i = 0; i < 4; i++)
        tile[ty + 8 * i][tx] = src[(size_t)(k0 + ty + 8 * i) * N + n0 + tx];
    __syncthreads();
    #pragma unroll
    for (int i = 0; i < 4; i++) {
        int nn = ty + 8 * i, kk = tx;
        float v = tile[kk][nn];
        u16 h, l; split1(v, h, l);
        size_t o = (size_t)off + (size_t)(n0 + nn) * K + k0 + kk;
        g_w_h[o] = h;
        g_w_l[o] = l;
    }
}

// layernorm -> split bf16 hi/lo.  DST: 0 -> g_aq, 1 -> g_as
template <int DST>
__global__ void ln_kernel(const float* __restrict__ x,
                          const float* __restrict__ gamma, const float* __restrict__ beta) {
    u16* yh = (DST == 0) ? g_aq_h : g_as_h;
    u16* yl = (DST == 0) ? g_aq_l : g_as_l;
    int row = blockIdx.x;
    int t = threadIdx.x;
    const float4* xin = (const float4*)(x + (size_t)row * DIM);
    float4 v = xin[t];
    float s1 = v.x + v.y + v.z + v.w;
    float s2 = v.x*v.x + v.y*v.y + v.z*v.z + v.w*v.w;
    #pragma unroll
    for (int o = 16; o; o >>= 1) {
        s1 += __shfl_xor_sync(0xffffffffu, s1, o);
        s2 += __shfl_xor_sync(0xffffffffu, s2, o);
    }
    __shared__ float sh1[4], sh2[4];
    int w = t >> 5;
    if ((t & 31) == 0) { sh1[w] = s1; sh2[w] = s2; }
    __syncthreads();
    s1 = sh1[0] + sh1[1] + sh1[2] + sh1[3];
    s2 = sh2[0] + sh2[1] + sh2[2] + sh2[3];
    float mean = s1 * (1.0f / DIM);
    float var  = s2 * (1.0f / DIM) - mean * mean;
    float rstd = rsqrtf(var + LN_EPS);
    float4 gg = ((const float4*)gamma)[t];
    float4 bb = ((const float4*)beta)[t];
    float o0 = (v.x - mean) * rstd * gg.x + bb.x;
    float o1 = (v.y - mean) * rstd * gg.y + bb.y;
    float o2 = (v.z - mean) * rstd * gg.z + bb.z;
    float o3 = (v.w - mean) * rstd * gg.w + bb.w;
    u16 h0,h1,h2,h3,l0,l1,l2,l3;
    split1(o0,h0,l0); split1(o1,h1,l1); split1(o2,h2,l2); split1(o3,h3,l3);
    size_t off = (size_t)row * DIM + t * 4;
    *(u32*)(yh + off)     = pack2(h0, h1);
    *(u32*)(yh + off + 2) = pack2(h2, h3);
    *(u32*)(yl + off)     = pack2(l0, l1);
    *(u32*)(yl + off + 2) = pack2(l2, l3);
}

// column reductions over qs/ks/vs
__global__ void reduce_kernel() {
    int c = blockIdx.x * 128 + threadIdx.x;
    int r0 = blockIdx.y * 256;
    float sd = 0.f, sk = 0.f, sk2 = 0.f, sq2 = 0.f;
    for (int r = 0; r < 256; r++) {
        size_t idx = (size_t)(r0 + r) * DIM + c;
        float kk = g_ks[idx], vv = g_vs[idx], qq = g_qs[idx];
        sd += kk * vv; sk += kk; sk2 += kk * kk; sq2 += qq * qq;
    }
    atomicAdd(&g_red[c], sd);
    atomicAdd(&g_red[DIM + c], sk);
    #pragma unroll
    for (int o = 16; o; o >>= 1) {
        sq2 += __shfl_xor_sync(0xffffffffu, sq2, o);
        sk2 += __shfl_xor_sync(0xffffffffu, sk2, o);
    }
    __shared__ float sa[4], sb[4];
    if ((threadIdx.x & 31) == 0) { sa[threadIdx.x >> 5] = sq2; sb[threadIdx.x >> 5] = sk2; }
    __syncthreads();
    if (threadIdx.x == 0) {
        atomicAdd(&g_red[2 * DIM],     sa[0] + sa[1] + sa[2] + sa[3]);
        atomicAdd(&g_red[2 * DIM + 1], sb[0] + sb[1] + sb[2] + sb[3]);
    }
}

// attention finalize -> split bf16 into g_aq_h/l
__global__ void attn_kernel() {
    int row = blockIdx.x;
    int t = threadIdx.x;  // cols 4t..4t+3; head = t/16
    float rFq = rsqrtf(g_red[2 * DIM]);
    float rFk = rsqrtf(g_red[2 * DIM + 1]);
    const float nf = (float)NE;
    size_t base = (size_t)row * DIM;
    float4 q  = ((const float4*)(g_qs + base))[t];
    float4 v  = ((const float4*)(g_vs + base))[t];
    float4 dg = ((const float4*)(g_red))[t];
    float4 km = ((const float4*)(g_red + DIM))[t];
    float p = (q.x*km.x + q.y*km.y + q.z*km.z + q.w*km.w) * (rFq * rFk);
    #pragma unroll
    for (int o = 8; o; o >>= 1) p += __shfl_xor_sync(0xffffffffu, p, o);
    float inv = 1.0f / (p + nf);
    float s = rFq * rFk;
    float o0 = (q.x * s * dg.x + v.x * nf) * inv;
    float o1 = (q.y * s * dg.y + v.y * nf) * inv;
    float o2 = (q.z * s * dg.z + v.z * nf) * inv;
    float o3 = (q.w * s * dg.w + v.w * nf) * inv;
    u16 h0,h1,h2,h3,l0,l1,l2,l3;
    split1(o0,h0,l0); split1(o1,h1,l1); split1(o2,h2,l2); split1(o3,h3,l3);
    size_t off = base + t * 4;
    *(u32*)(g_aq_h + off)     = pack2(h0, h1);
    *(u32*)(g_aq_h + off + 2) = pack2(h2, h3);
    *(u32*)(g_aq_l + off)     = pack2(l0, l1);
    *(u32*)(g_aq_l + off + 2) = pack2(l2, l3);
}

// ---------------- split-bf16 tensor-core GEMM, cp.async double-buffered ----------------
// B = TRANSPOSED weights Wt[n][k]; B smem tile [128n][32k] identical layout to A.
// All ldmatrix loads NON-TRANS (B col-major == Bt row-major for mma row.col).
// C = Ah@Bh^T + Ah@Bl^T + Al@Bh^T  (+bias, epilogues)
// ASEL: 0 g_aq, 1 g_as, 2 g_ff     CSEL: 0 qs, 1 ks, 2 vs, 3 Carg, 4 g_ff(split)
// EPI 0: +bias  1: +bias+res  2: gelu(+bias)  3: +bias+res (res==Carg ok)
// stage (u16): A_h[4096] A_l[4096] B_h[4096] B_l[4096] = 32KB
#define STG_BYTES 32768
#define SMEM_DYN (2 * STG_BYTES)
template <int EPI, int ASEL, int CSEL>
__global__ void __launch_bounds__(256)
mma_gemm(int boff, const float* __restrict__ bias, const float* __restrict__ res,
         float* __restrict__ Carg, int M, int N, int K)
{
    const u16* Ah = (ASEL == 0) ? g_aq_h : (ASEL == 1) ? g_as_h : g_ff_h;
    const u16* Al = (ASEL == 0) ? g_aq_l : (ASEL == 1) ? g_as_l : g_ff_l;
    const u16* Bh = g_w_h + boff;
    const u16* Bl = g_w_l + boff;
    float* C = (CSEL == 0) ? g_qs : (CSEL == 1) ? g_ks : (CSEL == 2) ? g_vs : Carg;

    extern __shared__ __align__(16) u16 smem[];
    const int tid = threadIdx.x, lane = tid & 31, warp = tid >> 5;
    const int wm = warp >> 1, wn = warp & 1;            // 4 x 2 warp grid
    const int row0 = blockIdx.y * 128;
    const int col0 = blockIdx.x * 128;

    float acc[2][8][4];
    #pragma unroll
    for (int i = 0; i < 2; i++)
        #pragma unroll
        for (int j = 0; j < 8; j++)
            #pragma unroll
            for (int c = 0; c < 4; c++) acc[i][j][c] = 0.0f;

    const u32 sBase = smem_u32(smem);

    // A-fragment lane mapping (16 rows x 2 k-chunks)
    const int lrA = lane & 15, lgA = lane >> 4;
    // B-fragment lane mapping (non-trans): groups 0-7:(n0-7,c0) 8-15:(n0-7,c1)
    //                                      16-23:(n8-15,c0) 24-31:(n8-15,c1)
    const int lrB = (lane & 7) + ((lane >> 4) << 3);
    const int kcB = (lane >> 3) & 1;
    // fill mapping (same for A and B tiles)
    const int ar = tid >> 2, aq = tid & 3;

    const u32 dA0 = (u32)((ar)      * 32 + 8 * (aq ^ (((ar)      >> 1) & 3))) * 2;
    const u32 dA1 = (u32)((ar + 64) * 32 + 8 * (aq ^ (((ar + 64) >> 1) & 3))) * 2;

    const int nk = K >> 5;  // K/32 slabs

    auto load_stage = [&](int stage, int slab) {
        int k0 = slab << 5;
        u32 sb = sBase + stage * STG_BYTES;
        const u16* a0  = Ah + (size_t)(row0 + ar) * K + k0 + aq * 8;
        const u16* a1  = Ah + (size_t)(row0 + ar + 64) * K + k0 + aq * 8;
        const u16* a0l = Al + (size_t)(row0 + ar) * K + k0 + aq * 8;
        const u16* a1l = Al + (size_t)(row0 + ar + 64) * K + k0 + aq * 8;
        cpa16(sb + dA0, a0);
        cpa16(sb + dA1, a1);
        cpa16(sb + dA0 + 8192, a0l);
        cpa16(sb + dA1 + 8192, a1l);
        const u16* b0  = Bh + (size_t)(col0 + ar) * K + k0 + aq * 8;
        const u16* b1  = Bh + (size_t)(col0 + ar + 64) * K + k0 + aq * 8;
        const u16* b0l = Bl + (size_t)(col0 + ar) * K + k0 + aq * 8;
        const u16* b1l = Bl + (size_t)(col0 + ar + 64) * K + k0 + aq * 8;
        cpa16(sb + dA0 + 16384, b0);
        cpa16(sb + dA1 + 16384, b1);
        cpa16(sb + dA0 + 24576, b0l);
        cpa16(sb + dA1 + 24576, b1l);
        cp_commit();
    };

    load_stage(0, 0);

    for (int it = 0; it < nk; it++) {
        if (it + 1 < nk) {
            load_stage((it + 1) & 1, it + 1);
            cp_wait<1>();
        } else {
            cp_wait<0>();
        }
        __syncthreads();

        const u32 stA = sBase + (it & 1) * STG_BYTES;
        const u32 stB = stA + 16384;
        #pragma unroll
        for (int ks = 0; ks < 32; ks += 16) {
            u32 ahf[2][4], alf[2][4];
            #pragma unroll
            for (int i = 0; i < 2; i++) {
                int r = wm * 32 + i * 16 + lrA;
                int G = (ks >> 3) + lgA;
                u32 off = (u32)(r * 32 + 8 * (G ^ ((r >> 1) & 3))) * 2;
                ldsm_x4(ahf[i], stA + off);
                ldsm_x4(alf[i], stA + 8192 + off);
            }
            #pragma unroll
            for (int jp = 0; jp < 4; jp++) {
                int r = wn * 64 + jp * 16 + lrB;
                int G = (ks >> 3) + kcB;
                u32 off = (u32)(r * 32 + 8 * (G ^ ((r >> 1) & 3))) * 2;
                u32 bhf[4], blf[4];
                ldsm_x4(bhf, stB + off);
                ldsm_x4(blf, stB + 8192 + off);
                #pragma unroll
                for (int i = 0; i < 2; i++) {
                    #pragma unroll
                    for (int jj = 0; jj < 2; jj++) {
                        float* d = acc[i][jp * 2 + jj];
                        mma16816(d, ahf[i], bhf + 2 * jj);
                        mma16816(d, ahf[i], blf + 2 * jj);
                        mma16816(d, alf[i], bhf + 2 * jj);
                    }
                }
            }
        }
        __syncthreads();
    }

    // epilogue
    const int cg = lane >> 2, ct = lane & 3;
    #pragma unroll
    for (int i = 0; i < 2; i++) {
        #pragma unroll
        for (int jn = 0; jn < 8; jn++) {
            int col = col0 + wn * 64 + jn * 8 + ct * 2;
            float b0 = bias[col], b1 = bias[col + 1];
            #pragma unroll
            for (int h = 0; h < 2; h++) {
                int row = row0 + wm * 32 + i * 16 + cg + h * 8;
                size_t idx = (size_t)row * N + col;
                float v0 = acc[i][jn][h * 2 + 0] + b0;
                float v1 = acc[i][jn][h * 2 + 1] + b1;
                if (EPI == 1 || EPI == 3) {
                    float2 r2 = *(const float2*)(res + idx);
                    v0 += r2.x; v1 += r2.y;
                }
                if (EPI == 2) {
                    v0 = 0.5f * v0 * (1.0f + erff(v0 * 0.7071067811865476f));
                    v1 = 0.5f * v1 * (1.0f + erff(v1 * 0.7071067811865476f));
                }
                if (CSEL == 4) {
                    u16 hh0, hh1, ll0, ll1;
                    split1(v0, hh0, ll0);
                    split1(v1, hh1, ll1);
                    *(u32*)(g_ff_h + idx) = pack2(hh0, hh1);
                    *(u32*)(g_ff_l + idx) = pack2(ll0, ll1);
                } else {
                    *(float2*)(C + idx) = make_float2(v0, v1);
                }
            }
        }
    }
}

// ---------------- launcher ----------------
extern "C" void kernel_launch(void* const* d_in, const int* in_sizes, int n_in,
                              void* d_out_v, int out_size) {
    const float* q_in = (const float*)d_in[0];
    const float* s_in = (const float*)d_in[1];
    const float* Wq = (const float*)d_in[2];  const float* bq = (const float*)d_in[3];
    const float* Wk = (const float*)d_in[4];  const float* bk = (const float*)d_in[5];
    const float* Wv = (const float*)d_in[6];  const float* bv = (const float*)d_in[7];
    const float* Wh = (const float*)d_in[8];  const float* bh = (const float*)d_in[9];
    const float* lnkg = (const float*)d_in[10]; const float* lnkb = (const float*)d_in[11];
    const float* lnqg = (const float*)d_in[12]; const float* lnqb = (const float*)d_in[13];
    const float* ln2g = (const float*)d_in[14]; const float* ln2b = (const float*)d_in[15];
    const float* W1 = (const float*)d_in[16]; const float* b1 = (const float*)d_in[17];
    const float* W2 = (const float*)d_in[18]; const float* b2 = (const float*)d_in[19];
    float* out = (float*)d_out_v;

    cudaFuncSetAttribute(mma_gemm<0,0,0>, cudaFuncAttributeMaxDynamicSharedMemorySize, SMEM_DYN);
    cudaFuncSetAttribute(mma_gemm<0,1,1>, cudaFuncAttributeMaxDynamicSharedMemorySize, SMEM_DYN);
    cudaFuncSetAttribute(mma_gemm<0,1,2>, cudaFuncAttributeMaxDynamicSharedMemorySize, SMEM_DYN);
    cudaFuncSetAttribute(mma_gemm<1,0,3>, cudaFuncAttributeMaxDynamicSharedMemorySize, SMEM_DYN);
    cudaFuncSetAttribute(mma_gemm<2,1,4>, cudaFuncAttributeMaxDynamicSharedMemorySize, SMEM_DYN);
    cudaFuncSetAttribute(mma_gemm<3,2,3>, cudaFuncAttributeMaxDynamicSharedMemorySize, SMEM_DYN);

    zero_red_kernel<<<(2 * DIM + 8 + 127) / 128, 128>>>();

    dim3 tb(32, 8);
    wsplit_t_kernel<<<dim3(512/32, 512/32), tb>>>(Wq, OFF_Q, 512, 512);
    wsplit_t_kernel<<<dim3(512/32, 512/32), tb>>>(Wk, OFF_K, 512, 512);
    wsplit_t_kernel<<<dim3(512/32, 512/32), tb>>>(Wv, OFF_V, 512, 512);
    wsplit_t_kernel<<<dim3(512/32, 512/32), tb>>>(Wh, OFF_H, 512, 512);
    wsplit_t_kernel<<<dim3(2048/32, 512/32), tb>>>(W1, OFF_1, 512, 2048);   // W1[512][2048] -> Wt[2048][512]
    wsplit_t_kernel<<<dim3(512/32, 2048/32), tb>>>(W2, OFF_2, 2048, 512);   // W2[2048][512] -> Wt[512][2048]

    ln_kernel<0><<<NE, 128>>>(q_in, lnqg, lnqb);   // ln_qry -> aq
    ln_kernel<1><<<NE, 128>>>(s_in, lnkg, lnkb);   // ln_src -> as

    dim3 blk(256);
    dim3 gD(DIM / 128, NE / 128);
    mma_gemm<0, 0, 0><<<gD, blk, SMEM_DYN>>>(OFF_Q, bq, nullptr, nullptr, NE, DIM, DIM);  // qs
    mma_gemm<0, 1, 1><<<gD, blk, SMEM_DYN>>>(OFF_K, bk, nullptr, nullptr, NE, DIM, DIM);  // ks
    mma_gemm<0, 1, 2><<<gD, blk, SMEM_DYN>>>(OFF_V, bv, nullptr, nullptr, NE, DIM, DIM);  // vs

    reduce_kernel<<<dim3(DIM / 128, 256), 128>>>();
    attn_kernel<<<NE, 128>>>();                    // -> aq (split bf16 attn_output)

    // h_pre_ffn = source + attn @ Wh + bh -> out
    mma_gemm<1, 0, 3><<<gD, blk, SMEM_DYN>>>(OFF_H, bh, s_in, out, NE, DIM, DIM);
    // y = LN(out) -> as
    ln_kernel<1><<<NE, 128>>>(out, ln2g, ln2b);
    // ffn = gelu(y @ W1 + b1) -> g_ff (split bf16)
    mma_gemm<2, 1, 4><<<dim3(DFF / 128, NE / 128), blk, SMEM_DYN>>>(OFF_1, b1, nullptr, nullptr, NE, DFF, DIM);
    // out = out + ffn @ W2 + b2
    mma_gemm<3, 2, 3><<<gD, blk, SMEM_DYN>>>(OFF_2, b2, out, out, NE, DIM, DFF);
}

// round 10
// speedup vs baseline: 1.2994x; 1.2994x over previous
#include <cuda_runtime.h>
#include <math.h>

#define NE   65536
#define DIM  512
#define DFF  2048
#define LN_EPS 1e-5f

typedef unsigned short u16;
typedef unsigned int   u32;

// ---------------- scratch (device globals; no allocations) ----------------
__device__ __align__(16) float g_qs [(size_t)NE * DIM];
__device__ __align__(16) float g_ks [(size_t)NE * DIM];
__device__ __align__(16) float g_vs [(size_t)NE * DIM];
__device__ __align__(16) u16 g_aq_h[(size_t)NE * DIM];  // ln_qry, later attn_output
__device__ __align__(16) u16 g_aq_l[(size_t)NE * DIM];
__device__ __align__(16) u16 g_as_h[(size_t)NE * DIM];  // ln_src, later y (ln2 out)
__device__ __align__(16) u16 g_as_l[(size_t)NE * DIM];
__device__ __align__(16) u16 g_ff_h[(size_t)NE * DFF];  // gelu output
__device__ __align__(16) u16 g_ff_l[(size_t)NE * DFF];
#define OFF_Q 0
#define OFF_K (512*512)
#define OFF_V (2*512*512)
#define OFF_H (3*512*512)
#define OFF_1 (4*512*512)
#define OFF_2 (4*512*512 + 512*2048)
#define W_TOT (4*512*512 + 2*512*2048)
__device__ __align__(16) u16 g_w_h[W_TOT];
__device__ __align__(16) u16 g_w_l[W_TOT];
// [0,DIM)=diag  [DIM,2DIM)=ksum  [2DIM]=|qs|^2  [2DIM+1]=|ks|^2
__device__ __align__(16) float g_red[2 * DIM + 8];

// ---------------- bf16-as-bits helpers ----------------
__device__ __forceinline__ u16 f2bf(float x) {
    u32 u = __float_as_uint(x);
    u32 r = u + 0x7FFFu + ((u >> 16) & 1u);   // round-to-nearest-even
    return (u16)(r >> 16);
}
__device__ __forceinline__ float bf2f(u16 h) {
    return __uint_as_float(((u32)h) << 16);
}
__device__ __forceinline__ void split1(float x, u16& h, u16& l) {
    h = f2bf(x);
    l = f2bf(x - bf2f(h));
}
__device__ __forceinline__ u32 pack2(u16 a, u16 b) {
    return (u32)a | ((u32)b << 16);
}

__device__ __forceinline__ u32 smem_u32(const void* p) {
    return (u32)__cvta_generic_to_shared(p);
}
__device__ __forceinline__ void ldsm_x4(u32* r, u32 a) {
    asm volatile("ldmatrix.sync.aligned.m8n8.x4.shared.b16 {%0,%1,%2,%3}, [%4];"
                 : "=r"(r[0]), "=r"(r[1]), "=r"(r[2]), "=r"(r[3]) : "r"(a));
}
__device__ __forceinline__ void ldsm_x4t(u32* r, u32 a) {
    asm volatile("ldmatrix.sync.aligned.m8n8.x4.trans.shared.b16 {%0,%1,%2,%3}, [%4];"
                 : "=r"(r[0]), "=r"(r[1]), "=r"(r[2]), "=r"(r[3]) : "r"(a));
}
__device__ __forceinline__ void mma16816(float* d, const u32* a, const u32* b) {
    asm volatile("mma.sync.aligned.m16n8k16.row.col.f32.bf16.bf16.f32 "
                 "{%0,%1,%2,%3}, {%4,%5,%6,%7}, {%8,%9}, {%0,%1,%2,%3};"
                 : "+f"(d[0]), "+f"(d[1]), "+f"(d[2]), "+f"(d[3])
                 : "r"(a[0]), "r"(a[1]), "r"(a[2]), "r"(a[3]), "r"(b[0]), "r"(b[1]));
}
__device__ __forceinline__ void cpa16(u32 dst, const void* src) {
    asm volatile("cp.async.cg.shared.global [%0], [%1], 16;" :: "r"(dst), "l"(src));
}
__device__ __forceinline__ void cp_commit() {
    asm volatile("cp.async.commit_group;");
}
template <int N>
__device__ __forceinline__ void cp_wait() {
    asm volatile("cp.async.wait_group %0;" :: "n"(N));
}

// ---------------- small kernels ----------------
__global__ void zero_red_kernel() {
    int i = blockIdx.x * blockDim.x + threadIdx.x;
    if (i < 2 * DIM + 8) g_red[i] = 0.0f;
}

__global__ void wsplit_kernel(const float* __restrict__ src, int off, int n4) {
    int i = blockIdx.x * 256 + threadIdx.x;
    if (i < n4) {
        float4 v = ((const float4*)src)[i];
        u16 h0,h1,h2,h3,l0,l1,l2,l3;
        split1(v.x,h0,l0); split1(v.y,h1,l1); split1(v.z,h2,l2); split1(v.w,h3,l3);
        size_t o = (size_t)off + (size_t)i * 4;
        *(u32*)(g_w_h + o)     = pack2(h0, h1);
        *(u32*)(g_w_h + o + 2) = pack2(h2, h3);
        *(u32*)(g_w_l + o)     = pack2(l0, l1);
        *(u32*)(g_w_l + o + 2) = pack2(l2, l3);
    }
}

// layernorm -> split bf16 hi/lo.  DST: 0 -> g_aq, 1 -> g_as
template <int DST>
__global__ void ln_kernel(const float* __restrict__ x,
                          const float* __restrict__ gamma, const float* __restrict__ beta) {
    u16* yh = (DST == 0) ? g_aq_h : g_as_h;
    u16* yl = (DST == 0) ? g_aq_l : g_as_l;
    int row = blockIdx.x;
    int t = threadIdx.x;
    const float4* xin = (const float4*)(x + (size_t)row * DIM);
    float4 v = xin[t];
    float s1 = v.x + v.y + v.z + v.w;
    float s2 = v.x*v.x + v.y*v.y + v.z*v.z + v.w*v.w;
    #pragma unroll
    for (int o = 16; o; o >>= 1) {
        s1 += __shfl_xor_sync(0xffffffffu, s1, o);
        s2 += __shfl_xor_sync(0xffffffffu, s2, o);
    }
    __shared__ float sh1[4], sh2[4];
    int w = t >> 5;
    if ((t & 31) == 0) { sh1[w] = s1; sh2[w] = s2; }
    __syncthreads();
    s1 = sh1[0] + sh1[1] + sh1[2] + sh1[3];
    s2 = sh2[0] + sh2[1] + sh2[2] + sh2[3];
    float mean = s1 * (1.0f / DIM);
    float var  = s2 * (1.0f / DIM) - mean * mean;
    float rstd = rsqrtf(var + LN_EPS);
    float4 gg = ((const float4*)gamma)[t];
    float4 bb = ((const float4*)beta)[t];
    float o0 = (v.x - mean) * rstd * gg.x + bb.x;
    float o1 = (v.y - mean) * rstd * gg.y + bb.y;
    float o2 = (v.z - mean) * rstd * gg.z + bb.z;
    float o3 = (v.w - mean) * rstd * gg.w + bb.w;
    u16 h0,h1,h2,h3,l0,l1,l2,l3;
    split1(o0,h0,l0); split1(o1,h1,l1); split1(o2,h2,l2); split1(o3,h3,l3);
    size_t off = (size_t)row * DIM + t * 4;
    *(u32*)(yh + off)     = pack2(h0, h1);
    *(u32*)(yh + off + 2) = pack2(h2, h3);
    *(u32*)(yl + off)     = pack2(l0, l1);
    *(u32*)(yl + off + 2) = pack2(l2, l3);
}

// column reductions over qs/ks/vs
__global__ void reduce_kernel() {
    int c = blockIdx.x * 128 + threadIdx.x;
    int r0 = blockIdx.y * 256;
    float sd = 0.f, sk = 0.f, sk2 = 0.f, sq2 = 0.f;
    for (int r = 0; r < 256; r++) {
        size_t idx = (size_t)(r0 + r) * DIM + c;
        float kk = g_ks[idx], vv = g_vs[idx], qq = g_qs[idx];
        sd += kk * vv; sk += kk; sk2 += kk * kk; sq2 += qq * qq;
    }
    atomicAdd(&g_red[c], sd);
    atomicAdd(&g_red[DIM + c], sk);
    #pragma unroll
    for (int o = 16; o; o >>= 1) {
        sq2 += __shfl_xor_sync(0xffffffffu, sq2, o);
        sk2 += __shfl_xor_sync(0xffffffffu, sk2, o);
    }
    __shared__ float sa[4], sb[4];
    if ((threadIdx.x & 31) == 0) { sa[threadIdx.x >> 5] = sq2; sb[threadIdx.x >> 5] = sk2; }
    __syncthreads();
    if (threadIdx.x == 0) {
        atomicAdd(&g_red[2 * DIM],     sa[0] + sa[1] + sa[2] + sa[3]);
        atomicAdd(&g_red[2 * DIM + 1], sb[0] + sb[1] + sb[2] + sb[3]);
    }
}

// attention finalize -> split bf16 into g_aq_h/l
__global__ void attn_kernel() {
    int row = blockIdx.x;
    int t = threadIdx.x;  // cols 4t..4t+3; head = t/16
    float rFq = rsqrtf(g_red[2 * DIM]);
    float rFk = rsqrtf(g_red[2 * DIM + 1]);
    const float nf = (float)NE;
    size_t base = (size_t)row * DIM;
    float4 q  = ((const float4*)(g_qs + base))[t];
    float4 v  = ((const float4*)(g_vs + base))[t];
    float4 dg = ((const float4*)(g_red))[t];
    float4 km = ((const float4*)(g_red + DIM))[t];
    float p = (q.x*km.x + q.y*km.y + q.z*km.z + q.w*km.w) * (rFq * rFk);
    #pragma unroll
    for (int o = 8; o; o >>= 1) p += __shfl_xor_sync(0xffffffffu, p, o);
    float inv = 1.0f / (p + nf);
    float s = rFq * rFk;
    float o0 = (q.x * s * dg.x + v.x * nf) * inv;
    float o1 = (q.y * s * dg.y + v.y * nf) * inv;
    float o2 = (q.z * s * dg.z + v.z * nf) * inv;
    float o3 = (q.w * s * dg.w + v.w * nf) * inv;
    u16 h0,h1,h2,h3,l0,l1,l2,l3;
    split1(o0,h0,l0); split1(o1,h1,l1); split1(o2,h2,l2); split1(o3,h3,l3);
    size_t off = base + t * 4;
    *(u32*)(g_aq_h + off)     = pack2(h0, h1);
    *(u32*)(g_aq_h + off + 2) = pack2(h2, h3);
    *(u32*)(g_aq_l + off)     = pack2(l0, l1);
    *(u32*)(g_aq_l + off + 2) = pack2(l2, l3);
}

// ---------------- split-bf16 tensor-core GEMM, 3-stage cp.async, 1 sync/slab ----------------
// C = (Ah+Al)@(Bh+Bl) ~= Ah@Bh + Ah@Bl + Al@Bh  (+bias, epilogues)
// ASEL: 0 -> g_aq, 1 -> g_as, 2 -> g_ff     CSEL: 0 qs, 1 ks, 2 vs, 3 Carg, 4 g_ff(split)
// EPI 0: +bias   EPI 1: +bias+res   EPI 2: gelu(+bias)   EPI 3: +bias+res (res==Carg ok)
// dynamic smem: 3 stages x 32KB.  Stage (u16): A_h[4096] A_l[4096] B_h[4096] B_l[4096]
#define STG_BYTES 32768
#define SMEM_DYN (3 * STG_BYTES)
template <int EPI, int ASEL, int CSEL>
__global__ void __launch_bounds__(256)
mma_gemm(int boff, const float* __restrict__ bias, const float* __restrict__ res,
         float* __restrict__ Carg, int M, int N, int K)
{
    const u16* Ah = (ASEL == 0) ? g_aq_h : (ASEL == 1) ? g_as_h : g_ff_h;
    const u16* Al = (ASEL == 0) ? g_aq_l : (ASEL == 1) ? g_as_l : g_ff_l;
    const u16* Bh = g_w_h + boff;
    const u16* Bl = g_w_l + boff;
    float* C = (CSEL == 0) ? g_qs : (CSEL == 1) ? g_ks : (CSEL == 2) ? g_vs : Carg;

    extern __shared__ __align__(16) u16 smem[];
    const int tid = threadIdx.x, lane = tid & 31, warp = tid >> 5;
    const int wm = warp >> 1, wn = warp & 1;            // 4 x 2 warp grid
    const int row0 = blockIdx.y * 128;
    const int col0 = blockIdx.x * 128;

    float acc[2][8][4];
    #pragma unroll
    for (int i = 0; i < 2; i++)
        #pragma unroll
        for (int j = 0; j < 8; j++)
            #pragma unroll
            for (int c = 0; c < 4; c++) acc[i][j][c] = 0.0f;

    const u32 sBase = smem_u32(smem);

    const int lrA = lane & 15, lgA = lane >> 4;
    const int lkB = (lane & 7) + ((lane >> 3) & 1) * 8;
    const int lgB = lane >> 4;
    const int ar = tid >> 2, aq = tid & 3;
    const int br = tid >> 4, bq = tid & 15;

    // precomputed per-thread smem dst offsets (bytes, relative to stage base)
    u32 dA0 = (u32)((ar)      * 32 + 8 * (aq ^ (((ar)      >> 1) & 3))) * 2;
    u32 dA1 = (u32)((ar + 64) * 32 + 8 * (aq ^ (((ar + 64) >> 1) & 3))) * 2;
    u32 dB0 = (u32)((br)      * 128 + 8 * (bq ^ ((br)      & 7))) * 2 + 16384;
    u32 dB1 = (u32)((br + 16) * 128 + 8 * (bq ^ ((br + 16) & 7))) * 2 + 16384;

    const int nk = K >> 5;  // K/32 slabs (16 or 64)

    auto load_stage = [&](int stage, int slab) {
        int k0 = slab << 5;
        u32 sb = sBase + stage * STG_BYTES;
        const u16* a0  = Ah + (size_t)(row0 + ar) * K + k0 + aq * 8;
        const u16* a1  = Ah + (size_t)(row0 + ar + 64) * K + k0 + aq * 8;
        const u16* a0l = Al + (size_t)(row0 + ar) * K + k0 + aq * 8;
        const u16* a1l = Al + (size_t)(row0 + ar + 64) * K + k0 + aq * 8;
        cpa16(sb + dA0, a0);
        cpa16(sb + dA1, a1);
        cpa16(sb + dA0 + 8192, a0l);
        cpa16(sb + dA1 + 8192, a1l);
        const u16* b0  = Bh + (size_t)(k0 + br) * N + col0 + bq * 8;
        const u16* b1  = Bh + (size_t)(k0 + br + 16) * N + col0 + bq * 8;
        const u16* b0l = Bl + (size_t)(k0 + br) * N + col0 + bq * 8;
        const u16* b1l = Bl + (size_t)(k0 + br + 16) * N + col0 + bq * 8;
        cpa16(sb + dB0, b0);
        cpa16(sb + dB1, b1);
        cpa16(sb + dB0 + 8192, b0l);
        cpa16(sb + dB1 + 8192, b1l);
        cp_commit();
    };

    // prologue: 2 stages in flight
    load_stage(0, 0);
    load_stage(1, 1);

    int stage = 0;
    for (int it = 0; it < nk; it++) {
        if (it + 1 < nk) cp_wait<1>(); else cp_wait<0>();
        __syncthreads();   // single barrier per slab: closes previous slab's reads AND opens this one

        const u32 stA = sBase + stage * STG_BYTES;
        const u32 stB = stA + 16384;
        #pragma unroll
        for (int ks = 0; ks < 32; ks += 16) {
            u32 ahf[2][4], alf[2][4];
            #pragma unroll
            for (int i = 0; i < 2; i++) {
                int r = wm * 32 + i * 16 + lrA;
                int G = (ks >> 3) + lgA;
                u32 off = (u32)(r * 32 + 8 * (G ^ ((r >> 1) & 3))) * 2;
                ldsm_x4(ahf[i], stA + off);
                ldsm_x4(alf[i], stA + 8192 + off);
            }
            int kB = ks + lkB;
            int swb = kB & 7;
            #pragma unroll
            for (int jp = 0; jp < 4; jp++) {
                int G = wn * 8 + jp * 2 + lgB;
                u32 off = (u32)(kB * 128 + 8 * (G ^ swb)) * 2;
                u32 bhf[4], blf[4];
                ldsm_x4t(bhf, stB + off);
                ldsm_x4t(blf, stB + 8192 + off);
                #pragma unroll
                for (int i = 0; i < 2; i++) {
                    #pragma unroll
                    for (int jj = 0; jj < 2; jj++) {
                        float* d = acc[i][jp * 2 + jj];
                        mma16816(d, ahf[i], bhf + 2 * jj);
                        mma16816(d, ahf[i], blf + 2 * jj);
                        mma16816(d, alf[i], bhf + 2 * jj);
                    }
                }
            }
        }
        // refill the stage consumed 2 iterations ago (its readers finished before
        // the barrier at the top of THIS iteration) — no trailing barrier needed.
        if (it + 2 < nk) {
            int ns = stage + 2;
            if (ns >= 3) ns -= 3;
            load_stage(ns, it + 2);
        }
        stage = (stage == 2) ? 0 : stage + 1;
    }

    // epilogue
    const int cg = lane >> 2, ct = lane & 3;
    #pragma unroll
    for (int i = 0; i < 2; i++) {
        #pragma unroll
        for (int jn = 0; jn < 8; jn++) {
            int col = col0 + wn * 64 + jn * 8 + ct * 2;
            float b0 = bias[col], b1 = bias[col + 1];
            #pragma unroll
            for (int h = 0; h < 2; h++) {
                int row = row0 + wm * 32 + i * 16 + cg + h * 8;
                size_t idx = (size_t)row * N + col;
                float v0 = acc[i][jn][h * 2 + 0] + b0;
                float v1 = acc[i][jn][h * 2 + 1] + b1;
                if (EPI == 1 || EPI == 3) {
                    float2 r2 = *(const float2*)(res + idx);
                    v0 += r2.x; v1 += r2.y;
                }
                if (EPI == 2) {
                    v0 = 0.5f * v0 * (1.0f + erff(v0 * 0.7071067811865476f));
                    v1 = 0.5f * v1 * (1.0f + erff(v1 * 0.7071067811865476f));
                }
                if (CSEL == 4) {
                    u16 hh0, hh1, ll0, ll1;
                    split1(v0, hh0, ll0);
                    split1(v1, hh1, ll1);
                    *(u32*)(g_ff_h + idx) = pack2(hh0, hh1);
                    *(u32*)(g_ff_l + idx) = pack2(ll0, ll1);
                } else {
                    *(float2*)(C + idx) = make_float2(v0, v1);
                }
            }
        }
    }
}

// ---------------- launcher ----------------
extern "C" void kernel_launch(void* const* d_in, const int* in_sizes, int n_in,
                              void* d_out_v, int out_size) {
    const float* q_in = (const float*)d_in[0];
    const float* s_in = (const float*)d_in[1];
    const float* Wq = (const float*)d_in[2];  const float* bq = (const float*)d_in[3];
    const float* Wk = (const float*)d_in[4];  const float* bk = (const float*)d_in[5];
    const float* Wv = (const float*)d_in[6];  const float* bv = (const float*)d_in[7];
    const float* Wh = (const float*)d_in[8];  const float* bh = (const float*)d_in[9];
    const float* lnkg = (const float*)d_in[10]; const float* lnkb = (const float*)d_in[11];
    const float* lnqg = (const float*)d_in[12]; const float* lnqb = (const float*)d_in[13];
    const float* ln2g = (const float*)d_in[14]; const float* ln2b = (const float*)d_in[15];
    const float* W1 = (const float*)d_in[16]; const float* b1 = (const float*)d_in[17];
    const float* W2 = (const float*)d_in[18]; const float* b2 = (const float*)d_in[19];
    float* out = (float*)d_out_v;

    cudaFuncSetAttribute(mma_gemm<0,0,0>, cudaFuncAttributeMaxDynamicSharedMemorySize, SMEM_DYN);
    cudaFuncSetAttribute(mma_gemm<0,1,1>, cudaFuncAttributeMaxDynamicSharedMemorySize, SMEM_DYN);
    cudaFuncSetAttribute(mma_gemm<0,1,2>, cudaFuncAttributeMaxDynamicSharedMemorySize, SMEM_DYN);
    cudaFuncSetAttribute(mma_gemm<1,0,3>, cudaFuncAttributeMaxDynamicSharedMemorySize, SMEM_DYN);
    cudaFuncSetAttribute(mma_gemm<2,1,4>, cudaFuncAttributeMaxDynamicSharedMemorySize, SMEM_DYN);
    cudaFuncSetAttribute(mma_gemm<3,2,3>, cudaFuncAttributeMaxDynamicSharedMemorySize, SMEM_DYN);

    dim3 blk(256);
    dim3 gD(DIM / 128, NE / 128);

    // Launch order arranged so launch #6 (ncu -s 5 -c 1) is a GEMM.
    wsplit_kernel<<<(512*512/4 + 255)/256, 256>>>(Wq, OFF_Q, 512*512/4);        // 1
    ln_kernel<0><<<NE, 128>>>(q_in, lnqg, lnqb);                                 // 2: ln_qry -> aq
    zero_red_kernel<<<(2 * DIM + 8 + 127) / 128, 128>>>();                       // 3
    wsplit_kernel<<<(512*512/4 + 255)/256, 256>>>(Wk, OFF_K, 512*512/4);        // 4
    wsplit_kernel<<<(512*512/4 + 255)/256, 256>>>(Wv, OFF_V, 512*512/4);        // 5
    mma_gemm<0, 0, 0><<<gD, blk, SMEM_DYN>>>(OFF_Q, bq, nullptr, nullptr, NE, DIM, DIM);  // 6: qs  <-- profiled
    ln_kernel<1><<<NE, 128>>>(s_in, lnkg, lnkb);                                 // 7: ln_src -> as
    mma_gemm<0, 1, 1><<<gD, blk, SMEM_DYN>>>(OFF_K, bk, nullptr, nullptr, NE, DIM, DIM);  // ks
    mma_gemm<0, 1, 2><<<gD, blk, SMEM_DYN>>>(OFF_V, bv, nullptr, nullptr, NE, DIM, DIM);  // vs
    wsplit_kernel<<<(512*512/4 + 255)/256, 256>>>(Wh, OFF_H, 512*512/4);
    wsplit_kernel<<<(512*2048/4 + 255)/256, 256>>>(W1, OFF_1, 512*2048/4);
    wsplit_kernel<<<(2048*512/4 + 255)/256, 256>>>(W2, OFF_2, 2048*512/4);

    reduce_kernel<<<dim3(DIM / 128, 256), 128>>>();
    attn_kernel<<<NE, 128>>>();                    // -> aq (split bf16 attn_output)

    // h_pre_ffn = source + attn @ Wh + bh -> out
    mma_gemm<1, 0, 3><<<gD, blk, SMEM_DYN>>>(OFF_H, bh, s_in, out, NE, DIM, DIM);
    // y = LN(out) -> as
    ln_kernel<1><<<NE, 128>>>(out, ln2g, ln2b);
    // ffn = gelu(y @ W1 + b1) -> g_ff (split bf16)
    mma_gemm<2, 1, 4><<<dim3(DFF / 128, NE / 128), blk, SMEM_DYN>>>(OFF_1, b1, nullptr, nullptr, NE, DFF, DIM);
    // out = out + ffn @ W2 + b2
    mma_gemm<3, 2, 3><<<gD, blk, SMEM_DYN>>>(OFF_2, b2, out, out, NE, DIM, DFF);
}